// round 12
// baseline (speedup 1.0000x reference)
#include <cuda_runtime.h>
#include <cstdint>

// AdaptiveEdgeSparsifier: per-row (4096) exact k-th-largest threshold, then
// out = (adj >= kth) ? adj : 0.
//
// R12: R10 structure (TMA bulk load -> smem row, window-collect select)
// pipelined across TWO rows per CTA with double-buffered smem: both TMA
// loads are issued up front, so row 1 streams from DRAM while row 0's
// select/histogram phases run. Output is thresholded straight out of smem
// registers and stored with STG.128 (no STS/fence/TMA-out round-trip),
// cutting smem-port traffic from ~80 KB to ~48 KB per row. Exact 32-bit
// block descent over the smem row remains the never-taken fallback.

#define N_COLS    4096
#define TPB       256
#define ROW_BYTES (N_COLS * 4)
#define MAXCOLL   1024
#define MAXB      32

// u-domain window (raw bits of negative floats): u in [UA,UB) <=> f in
// (-0.66015625, -0.3984375], +-6.3 sigma around the per-row 0.30-quantile
// (~ -0.5237 +- 0.0206) of 4096 N(0,1) samples. For negatives key = ~u;
// bin = (UB-1-u) >> 15 is monotone increasing in f. 186 bins.
#define UA        0xBECC0000u
#define UB        0xBF290000u
#define BIN_SHIFT 15
#define HI_STRICT (-0.3984375f)   /* count(f > HI_STRICT) == count above window */

__device__ __forceinline__ unsigned f2key(float f) {
    unsigned u = __float_as_uint(f);
    return u ^ ((unsigned)((int)u >> 31) | 0x80000000u);
}
__device__ __forceinline__ float key2f(unsigned k) {
    unsigned u = (k & 0x80000000u) ? (k ^ 0x80000000u) : ~k;
    return __uint_as_float(u);
}

// Branch-free: count-above + capacity-guarded predicated append of in-window
// raw bits to s_act.
__device__ __forceinline__ void passA_elem(float fv, int& chi,
                                           unsigned curaddr, unsigned actbase)
{
    chi += (fv > HI_STRICT) ? 1 : 0;
    unsigned u = __float_as_uint(fv);
    asm volatile(
        "{ .reg .pred p, q; .reg .u32 d, t, a;\n"
        "  add.u32 d, %0, %1;\n"                    // d = u - UA
        "  setp.lt.u32 p, d, %2;\n"                 // in window?
        "  @p atom.shared.add.u32 t, [%3], 1;\n"
        "  setp.lt.and.u32 q, t, %5, p;\n"          // slot < cap
        "  @q mad.lo.u32 a, t, 4, %4;\n"
        "  @q st.shared.b32 [a], %0;\n}"
        :: "r"(u), "r"(0u - UA), "r"(UB - UA),
           "r"(curaddr), "r"(actbase), "r"((unsigned)MAXCOLL)
        : "memory");
}

__global__ void __launch_bounds__(TPB, 6)
topk_sparsify_kernel(const float* __restrict__ in,
                     float4* __restrict__ out,
                     int kth, int nrows)
{
    __shared__ __align__(16) float s_row[2][N_COLS];     // 32 KB, double buffer
    __shared__ unsigned s_act[MAXCOLL];                  // 4 KB
    __shared__ int      s_hist[192];
    __shared__ unsigned s_bucket[MAXB];
    __shared__ int      s_part[2][TPB / 32];
    __shared__ __align__(8) unsigned long long s_mbar[2];
    __shared__ int      s_chi, s_cur, s_cur2, s_j, s_m, s_nb, s_fb;
    __shared__ float    s_ft;

    const int tid  = threadIdx.x;
    const int lane = tid & 31;
    const size_t row0 = (size_t)blockIdx.x * 2;

    const unsigned mb0 = (unsigned)__cvta_generic_to_shared(&s_mbar[0]);

    if (tid == 0) {
        asm volatile("mbarrier.init.shared.b64 [%0], 1;" :: "r"(mb0)     : "memory");
        asm volatile("mbarrier.init.shared.b64 [%0], 1;" :: "r"(mb0 + 8) : "memory");
    }
    __syncthreads();

    // ---- issue BOTH row loads up front; row1 streams during row0's select ----
    if (tid == 0) {
#pragma unroll
        for (int b = 0; b < 2; ++b) {
            if (row0 + b < (size_t)nrows) {
                const unsigned mb = mb0 + 8u * b;
                const unsigned dst =
                    (unsigned)__cvta_generic_to_shared(&s_row[b][0]);
                asm volatile("mbarrier.arrive.expect_tx.shared.b64 _, [%0], %1;"
                             :: "r"(mb), "r"((unsigned)ROW_BYTES) : "memory");
                const float* src = in + (row0 + b) * N_COLS;
                asm volatile(
                    "cp.async.bulk.shared::cta.global.mbarrier::complete_tx::bytes "
                    "[%0], [%1], %2, [%3];"
                    :: "r"(dst), "l"(src), "r"((unsigned)ROW_BYTES), "r"(mb)
                    : "memory");
            }
        }
    }

#pragma unroll 1
    for (int b = 0; b < 2; ++b) {
        if (row0 + b >= (size_t)nrows) break;

        // ---- reset per-row scratch (barrier also closes previous row) ----
        __syncthreads();
        if (tid < 192) s_hist[tid] = 0;
        if (tid == 0) { s_chi = 0; s_cur = 0; s_cur2 = 0; s_fb = 0; }
        __syncthreads();

        // ---- wait for this row's TMA (parity 0; each mbar used once) ----
        asm volatile(
            "{ .reg .pred P;\n"
            "W%=: mbarrier.try_wait.parity.acquire.cta.shared::cta.b64 P, [%0], 0;\n"
            "  @!P bra W%=;\n}"
            :: "r"(mb0 + 8u * b) : "memory");

        const float4* sr = (const float4*)s_row[b];

        // ---- Pass A: count-above + collect in-window (LDS.128) ----
        {
            const unsigned curaddr = (unsigned)__cvta_generic_to_shared(&s_cur);
            const unsigned actbase = (unsigned)__cvta_generic_to_shared(s_act);
            int chi = 0;
#pragma unroll
            for (int i = 0; i < 4; ++i) {
                float4 v = sr[i * TPB + tid];
                passA_elem(v.x, chi, curaddr, actbase);
                passA_elem(v.y, chi, curaddr, actbase);
                passA_elem(v.z, chi, curaddr, actbase);
                passA_elem(v.w, chi, curaddr, actbase);
            }
            chi = __reduce_add_sync(0xFFFFFFFFu, chi);
            if (lane == 0) atomicAdd(&s_chi, chi);
        }
        __syncthreads();

        const int ncoll = s_cur;
        const int chi   = s_chi;
        const int nscan = (ncoll < MAXCOLL) ? ncoll : MAXCOLL;
        if (tid == 0 && ncoll > MAXCOLL) s_fb = 1;   // overflow -> fallback

        // ---- Pass B: histogram collected (~371) into 186 key-domain bins ----
        for (int i = tid; i < nscan; i += TPB) {
            unsigned u = s_act[i];
            atomicAdd(&s_hist[(UB - 1u - u) >> BIN_SHIFT], 1);
        }
        __syncthreads();

        // ---- Pass C: warp-0 suffix scan; bucket j*, rank m ----
        if (tid < 32) {
            int h[6];
            int lt = 0;
#pragma unroll
            for (int r = 0; r < 6; ++r) { h[r] = s_hist[lane * 6 + r]; lt += h[r]; }
            int x = lt;                                // suffix sum over lanes
#pragma unroll
            for (int d = 1; d < 32; d <<= 1) {
                int y = __shfl_down_sync(0xFFFFFFFFu, x, d);
                if (lane + d < 32) x += y;
            }
            const int cumbase = chi + x;               // count(bin >= 6*lane)
            int cand = -1, candcum = 0, candh = 0, pre = 0;
#pragma unroll
            for (int r = 0; r < 6; ++r) {
                int j   = lane * 6 + r;
                int cum = cumbase - pre;               // count(bin >= j)
                if (cum >= kth) { cand = j; candcum = cum; candh = h[r]; }
                pre += h[r];
            }
            int jstar = __reduce_max_sync(0xFFFFFFFFu, cand);
            if (cand == jstar && jstar >= 0) {         // unique owner lane
                s_j = jstar;
                s_m = kth - (candcum - candh);
                s_nb = candh;
                if (candh > MAXB) s_fb = 1;
            }
            if (lane == 0 && (jstar < 0 || chi >= kth)) s_fb = 1;
        }
        __syncthreads();

        float ft;
        if (!s_fb) {
            // ---- Pass D: gather bucket members (<= 32) as keys ----
            const unsigned ubhi = UB - 1u - ((unsigned)s_j << BIN_SHIFT);
            for (int i = tid; i < nscan; i += TPB) {
                unsigned u = s_act[i];
                if ((ubhi - u) < (1u << BIN_SHIFT)) {
                    int pos = atomicAdd(&s_cur2, 1);
                    s_bucket[pos] = ~u;                // key of negative float
                }
            }
            __syncthreads();

            // warp 0: m-th largest among <=32 keys (dup-safe)
            if (tid < 32) {
                const int nb = s_nb, m = s_m;
                unsigned kv = (lane < nb) ? s_bucket[lane] : 0u;
                for (int i = 1; i < m; ++i) {
                    unsigned mx   = __reduce_max_sync(0xFFFFFFFFu, kv);
                    unsigned ball = __ballot_sync(0xFFFFFFFFu, kv == mx);
                    if (lane == (int)(__ffs(ball) - 1)) kv = 0u;
                }
                unsigned t = __reduce_max_sync(0xFFFFFFFFu, kv);
                if (lane == 0) s_ft = key2f(t);
            }
            __syncthreads();
            ft = s_ft;
        } else {
            // ---- exact fallback: 32-bit MSB-first descent over smem row ----
            unsigned result = 0u;
#pragma unroll 1
            for (int bit = 31; bit >= 0; --bit) {
                const unsigned t = result | (1u << bit);
                int c = 0;
#pragma unroll
                for (int i = 0; i < 4; ++i) {
                    float4 v = sr[i * TPB + tid];
                    c += (f2key(v.x) >= t) ? 1 : 0;
                    c += (f2key(v.y) >= t) ? 1 : 0;
                    c += (f2key(v.z) >= t) ? 1 : 0;
                    c += (f2key(v.w) >= t) ? 1 : 0;
                }
                c = __reduce_add_sync(0xFFFFFFFFu, c);
                if (lane == 0) s_part[bit & 1][tid >> 5] = c;
                __syncthreads();
                int tot = 0;
#pragma unroll
                for (int w = 0; w < TPB / 32; ++w) tot += s_part[bit & 1][w];
                if (tot >= kth) { result = t; if (tot == kth) break; } // uniform
            }
            ft = key2f(result);
        }

        // ---- output: threshold from smem, STG.128 direct to GMEM ----
        {
            float4* q = out + (row0 + b) * (N_COLS / 4) + tid;
#pragma unroll
            for (int i = 0; i < 4; ++i) {
                float4 v = sr[i * TPB + tid];
                v.x = (v.x >= ft) ? v.x : 0.0f;
                v.y = (v.y >= ft) ? v.y : 0.0f;
                v.z = (v.z >= ft) ? v.z : 0.0f;
                v.w = (v.w >= ft) ? v.w : 0.0f;
                q[i * TPB] = v;
            }
        }
    }
}

extern "C" void kernel_launch(void* const* d_in, const int* in_sizes, int n_in,
                              void* d_out, int out_size)
{
    const float* in  = (const float*)d_in[0];
    float4*      out = (float4*)d_out;

    const int rows = in_sizes[0] / N_COLS;        // 8 * 4096 = 32768

    int k = (int)((double)N_COLS * (1.0 - 0.3));  // 2867, matches Python int()
    if (k < 1) k = 1;

    const int blocks = (rows + 1) / 2;
    topk_sparsify_kernel<<<blocks, TPB>>>(in, out, k, rows);
}

// round 13
// speedup vs baseline: 1.0050x; 1.0050x over previous
#include <cuda_runtime.h>
#include <cstdint>

// AdaptiveEdgeSparsifier: per-row (4096) exact k-th-largest threshold, then
// out = (adj >= kth) ? adj : 0.
//
// R12: R10 structure (TMA bulk load -> smem row, window-collect select)
// pipelined across TWO rows per CTA with double-buffered smem: both TMA
// loads are issued up front, so row 1 streams from DRAM while row 0's
// select/histogram phases run. Output is thresholded straight out of smem
// registers and stored with STG.128 (no STS/fence/TMA-out round-trip),
// cutting smem-port traffic from ~80 KB to ~48 KB per row. Exact 32-bit
// block descent over the smem row remains the never-taken fallback.

#define N_COLS    4096
#define TPB       256
#define ROW_BYTES (N_COLS * 4)
#define MAXCOLL   1024
#define MAXB      32

// u-domain window (raw bits of negative floats): u in [UA,UB) <=> f in
// (-0.66015625, -0.3984375], +-6.3 sigma around the per-row 0.30-quantile
// (~ -0.5237 +- 0.0206) of 4096 N(0,1) samples. For negatives key = ~u;
// bin = (UB-1-u) >> 15 is monotone increasing in f. 186 bins.
#define UA        0xBECC0000u
#define UB        0xBF290000u
#define BIN_SHIFT 15
#define HI_STRICT (-0.3984375f)   /* count(f > HI_STRICT) == count above window */

__device__ __forceinline__ unsigned f2key(float f) {
    unsigned u = __float_as_uint(f);
    return u ^ ((unsigned)((int)u >> 31) | 0x80000000u);
}
__device__ __forceinline__ float key2f(unsigned k) {
    unsigned u = (k & 0x80000000u) ? (k ^ 0x80000000u) : ~k;
    return __uint_as_float(u);
}

// Branch-free: count-above + capacity-guarded predicated append of in-window
// raw bits to s_act.
__device__ __forceinline__ void passA_elem(float fv, int& chi,
                                           unsigned curaddr, unsigned actbase)
{
    chi += (fv > HI_STRICT) ? 1 : 0;
    unsigned u = __float_as_uint(fv);
    asm volatile(
        "{ .reg .pred p, q; .reg .u32 d, t, a;\n"
        "  add.u32 d, %0, %1;\n"                    // d = u - UA
        "  setp.lt.u32 p, d, %2;\n"                 // in window?
        "  @p atom.shared.add.u32 t, [%3], 1;\n"
        "  setp.lt.and.u32 q, t, %5, p;\n"          // slot < cap
        "  @q mad.lo.u32 a, t, 4, %4;\n"
        "  @q st.shared.b32 [a], %0;\n}"
        :: "r"(u), "r"(0u - UA), "r"(UB - UA),
           "r"(curaddr), "r"(actbase), "r"((unsigned)MAXCOLL)
        : "memory");
}

__global__ void __launch_bounds__(TPB, 6)
topk_sparsify_kernel(const float* __restrict__ in,
                     float4* __restrict__ out,
                     int kth, int nrows)
{
    __shared__ __align__(16) float s_row[2][N_COLS];     // 32 KB, double buffer
    __shared__ unsigned s_act[MAXCOLL];                  // 4 KB
    __shared__ int      s_hist[192];
    __shared__ unsigned s_bucket[MAXB];
    __shared__ int      s_part[2][TPB / 32];
    __shared__ __align__(8) unsigned long long s_mbar[2];
    __shared__ int      s_chi, s_cur, s_cur2, s_j, s_m, s_nb, s_fb;
    __shared__ float    s_ft;

    const int tid  = threadIdx.x;
    const int lane = tid & 31;
    const size_t row0 = (size_t)blockIdx.x * 2;

    const unsigned mb0 = (unsigned)__cvta_generic_to_shared(&s_mbar[0]);

    if (tid == 0) {
        asm volatile("mbarrier.init.shared.b64 [%0], 1;" :: "r"(mb0)     : "memory");
        asm volatile("mbarrier.init.shared.b64 [%0], 1;" :: "r"(mb0 + 8) : "memory");
    }
    __syncthreads();

    // ---- issue BOTH row loads up front; row1 streams during row0's select ----
    if (tid == 0) {
#pragma unroll
        for (int b = 0; b < 2; ++b) {
            if (row0 + b < (size_t)nrows) {
                const unsigned mb = mb0 + 8u * b;
                const unsigned dst =
                    (unsigned)__cvta_generic_to_shared(&s_row[b][0]);
                asm volatile("mbarrier.arrive.expect_tx.shared.b64 _, [%0], %1;"
                             :: "r"(mb), "r"((unsigned)ROW_BYTES) : "memory");
                const float* src = in + (row0 + b) * N_COLS;
                asm volatile(
                    "cp.async.bulk.shared::cta.global.mbarrier::complete_tx::bytes "
                    "[%0], [%1], %2, [%3];"
                    :: "r"(dst), "l"(src), "r"((unsigned)ROW_BYTES), "r"(mb)
                    : "memory");
            }
        }
    }

#pragma unroll 1
    for (int b = 0; b < 2; ++b) {
        if (row0 + b >= (size_t)nrows) break;

        // ---- reset per-row scratch (barrier also closes previous row) ----
        __syncthreads();
        if (tid < 192) s_hist[tid] = 0;
        if (tid == 0) { s_chi = 0; s_cur = 0; s_cur2 = 0; s_fb = 0; }
        __syncthreads();

        // ---- wait for this row's TMA (parity 0; each mbar used once) ----
        asm volatile(
            "{ .reg .pred P;\n"
            "W%=: mbarrier.try_wait.parity.acquire.cta.shared::cta.b64 P, [%0], 0;\n"
            "  @!P bra W%=;\n}"
            :: "r"(mb0 + 8u * b) : "memory");

        const float4* sr = (const float4*)s_row[b];

        // ---- Pass A: count-above + collect in-window (LDS.128) ----
        {
            const unsigned curaddr = (unsigned)__cvta_generic_to_shared(&s_cur);
            const unsigned actbase = (unsigned)__cvta_generic_to_shared(s_act);
            int chi = 0;
#pragma unroll
            for (int i = 0; i < 4; ++i) {
                float4 v = sr[i * TPB + tid];
                passA_elem(v.x, chi, curaddr, actbase);
                passA_elem(v.y, chi, curaddr, actbase);
                passA_elem(v.z, chi, curaddr, actbase);
                passA_elem(v.w, chi, curaddr, actbase);
            }
            chi = __reduce_add_sync(0xFFFFFFFFu, chi);
            if (lane == 0) atomicAdd(&s_chi, chi);
        }
        __syncthreads();

        const int ncoll = s_cur;
        const int chi   = s_chi;
        const int nscan = (ncoll < MAXCOLL) ? ncoll : MAXCOLL;
        if (tid == 0 && ncoll > MAXCOLL) s_fb = 1;   // overflow -> fallback

        // ---- Pass B: histogram collected (~371) into 186 key-domain bins ----
        for (int i = tid; i < nscan; i += TPB) {
            unsigned u = s_act[i];
            atomicAdd(&s_hist[(UB - 1u - u) >> BIN_SHIFT], 1);
        }
        __syncthreads();

        // ---- Pass C: warp-0 suffix scan; bucket j*, rank m ----
        if (tid < 32) {
            int h[6];
            int lt = 0;
#pragma unroll
            for (int r = 0; r < 6; ++r) { h[r] = s_hist[lane * 6 + r]; lt += h[r]; }
            int x = lt;                                // suffix sum over lanes
#pragma unroll
            for (int d = 1; d < 32; d <<= 1) {
                int y = __shfl_down_sync(0xFFFFFFFFu, x, d);
                if (lane + d < 32) x += y;
            }
            const int cumbase = chi + x;               // count(bin >= 6*lane)
            int cand = -1, candcum = 0, candh = 0, pre = 0;
#pragma unroll
            for (int r = 0; r < 6; ++r) {
                int j   = lane * 6 + r;
                int cum = cumbase - pre;               // count(bin >= j)
                if (cum >= kth) { cand = j; candcum = cum; candh = h[r]; }
                pre += h[r];
            }
            int jstar = __reduce_max_sync(0xFFFFFFFFu, cand);
            if (cand == jstar && jstar >= 0) {         // unique owner lane
                s_j = jstar;
                s_m = kth - (candcum - candh);
                s_nb = candh;
                if (candh > MAXB) s_fb = 1;
            }
            if (lane == 0 && (jstar < 0 || chi >= kth)) s_fb = 1;
        }
        __syncthreads();

        float ft;
        if (!s_fb) {
            // ---- Pass D: gather bucket members (<= 32) as keys ----
            const unsigned ubhi = UB - 1u - ((unsigned)s_j << BIN_SHIFT);
            for (int i = tid; i < nscan; i += TPB) {
                unsigned u = s_act[i];
                if ((ubhi - u) < (1u << BIN_SHIFT)) {
                    int pos = atomicAdd(&s_cur2, 1);
                    s_bucket[pos] = ~u;                // key of negative float
                }
            }
            __syncthreads();

            // warp 0: m-th largest among <=32 keys (dup-safe)
            if (tid < 32) {
                const int nb = s_nb, m = s_m;
                unsigned kv = (lane < nb) ? s_bucket[lane] : 0u;
                for (int i = 1; i < m; ++i) {
                    unsigned mx   = __reduce_max_sync(0xFFFFFFFFu, kv);
                    unsigned ball = __ballot_sync(0xFFFFFFFFu, kv == mx);
                    if (lane == (int)(__ffs(ball) - 1)) kv = 0u;
                }
                unsigned t = __reduce_max_sync(0xFFFFFFFFu, kv);
                if (lane == 0) s_ft = key2f(t);
            }
            __syncthreads();
            ft = s_ft;
        } else {
            // ---- exact fallback: 32-bit MSB-first descent over smem row ----
            unsigned result = 0u;
#pragma unroll 1
            for (int bit = 31; bit >= 0; --bit) {
                const unsigned t = result | (1u << bit);
                int c = 0;
#pragma unroll
                for (int i = 0; i < 4; ++i) {
                    float4 v = sr[i * TPB + tid];
                    c += (f2key(v.x) >= t) ? 1 : 0;
                    c += (f2key(v.y) >= t) ? 1 : 0;
                    c += (f2key(v.z) >= t) ? 1 : 0;
                    c += (f2key(v.w) >= t) ? 1 : 0;
                }
                c = __reduce_add_sync(0xFFFFFFFFu, c);
                if (lane == 0) s_part[bit & 1][tid >> 5] = c;
                __syncthreads();
                int tot = 0;
#pragma unroll
                for (int w = 0; w < TPB / 32; ++w) tot += s_part[bit & 1][w];
                if (tot >= kth) { result = t; if (tot == kth) break; } // uniform
            }
            ft = key2f(result);
        }

        // ---- output: threshold from smem, STG.128 direct to GMEM ----
        {
            float4* q = out + (row0 + b) * (N_COLS / 4) + tid;
#pragma unroll
            for (int i = 0; i < 4; ++i) {
                float4 v = sr[i * TPB + tid];
                v.x = (v.x >= ft) ? v.x : 0.0f;
                v.y = (v.y >= ft) ? v.y : 0.0f;
                v.z = (v.z >= ft) ? v.z : 0.0f;
                v.w = (v.w >= ft) ? v.w : 0.0f;
                q[i * TPB] = v;
            }
        }
    }
}

extern "C" void kernel_launch(void* const* d_in, const int* in_sizes, int n_in,
                              void* d_out, int out_size)
{
    const float* in  = (const float*)d_in[0];
    float4*      out = (float4*)d_out;

    const int rows = in_sizes[0] / N_COLS;        // 8 * 4096 = 32768

    int k = (int)((double)N_COLS * (1.0 - 0.3));  // 2867, matches Python int()
    if (k < 1) k = 1;

    const int blocks = (rows + 1) / 2;
    topk_sparsify_kernel<<<blocks, TPB>>>(in, out, k, rows);
}

// round 14
// speedup vs baseline: 1.5506x; 1.5428x over previous
#include <cuda_runtime.h>
#include <cstdint>

// AdaptiveEdgeSparsifier: per-row (4096) exact k-th-largest threshold, then
// out = (adj >= kth) ? adj : 0.
//
// R13 = R10 (best: 182us) with exactly ONE change: the output tail.
// R10: LDS -> threshold -> STS -> fence -> TMA bulk store  (smem ~80 KB/row)
// R13: LDS -> threshold in regs -> STG.128 direct          (smem ~48 KB/row)
// The L1/smem port was the binding pipe at 85.7%; this cuts its traffic 40%
// and removes the single-thread bulk-store wait at block end. Everything
// else (1 row/CTA, TMA bulk load -> smem, window-collect select, 8 CTAs/SM)
// is unchanged from R10.

#define N_COLS    4096
#define TPB       256
#define ROW_BYTES (N_COLS * 4)
#define MAXCOLL   1024
#define MAXB      32

// u-domain window (raw bits of negative floats): u in [UA,UB) <=> f in
// (-0.66015625, -0.3984375], +-6.3 sigma around the per-row 0.30-quantile
// (~ -0.5237 +- 0.0206) of 4096 N(0,1) samples. For negatives key = ~u;
// bin = (UB-1-u) >> 15 is monotone increasing in f. 186 bins.
#define UA        0xBECC0000u
#define UB        0xBF290000u
#define BIN_SHIFT 15
#define HI_STRICT (-0.3984375f)   /* count(f > HI_STRICT) == count above window */

__device__ __forceinline__ unsigned f2key(float f) {
    unsigned u = __float_as_uint(f);
    return u ^ ((unsigned)((int)u >> 31) | 0x80000000u);
}
__device__ __forceinline__ float key2f(unsigned k) {
    unsigned u = (k & 0x80000000u) ? (k ^ 0x80000000u) : ~k;
    return __uint_as_float(u);
}

// Branch-free: count-above + capacity-guarded predicated append of in-window
// raw bits to s_act.
__device__ __forceinline__ void passA_elem(float fv, int& chi,
                                           unsigned curaddr, unsigned actbase)
{
    chi += (fv > HI_STRICT) ? 1 : 0;
    unsigned u = __float_as_uint(fv);
    asm volatile(
        "{ .reg .pred p, q; .reg .u32 d, t, a;\n"
        "  add.u32 d, %0, %1;\n"                    // d = u - UA
        "  setp.lt.u32 p, d, %2;\n"                 // in window?
        "  @p atom.shared.add.u32 t, [%3], 1;\n"
        "  setp.lt.and.u32 q, t, %5, p;\n"          // slot < cap
        "  @q mad.lo.u32 a, t, 4, %4;\n"
        "  @q st.shared.b32 [a], %0;\n}"
        :: "r"(u), "r"(0u - UA), "r"(UB - UA),
           "r"(curaddr), "r"(actbase), "r"((unsigned)MAXCOLL)
        : "memory");
}

__global__ void __launch_bounds__(TPB, 8)
topk_sparsify_kernel(const float* __restrict__ in,
                     float4* __restrict__ out,
                     int kth)
{
    __shared__ __align__(16) float s_row[N_COLS];        // 16 KB
    __shared__ unsigned s_act[MAXCOLL];                  // 4 KB
    __shared__ int      s_hist[192];
    __shared__ unsigned s_bucket[MAXB];
    __shared__ int      s_part[2][TPB / 32];
    __shared__ __align__(8) unsigned long long s_mbar;
    __shared__ int      s_chi, s_cur, s_cur2, s_j, s_m, s_nb, s_fb;
    __shared__ float    s_ft;

    const int tid  = threadIdx.x;
    const int lane = tid & 31;
    const unsigned rowaddr = (unsigned)__cvta_generic_to_shared(s_row);
    const unsigned mbar    = (unsigned)__cvta_generic_to_shared(&s_mbar);

    if (tid < 192) s_hist[tid] = 0;
    if (tid == 0) {
        s_chi = 0; s_cur = 0; s_cur2 = 0; s_fb = 0;
        asm volatile("mbarrier.init.shared.b64 [%0], 1;" :: "r"(mbar) : "memory");
    }
    __syncthreads();

    // ---- async bulk load: GMEM row -> SMEM (one thread) ----
    if (tid == 0) {
        asm volatile("mbarrier.arrive.expect_tx.shared.b64 _, [%0], %1;"
                     :: "r"(mbar), "r"((unsigned)ROW_BYTES) : "memory");
        const float* src = in + (size_t)blockIdx.x * N_COLS;
        asm volatile(
            "cp.async.bulk.shared::cta.global.mbarrier::complete_tx::bytes "
            "[%0], [%1], %2, [%3];"
            :: "r"(rowaddr), "l"(src), "r"((unsigned)ROW_BYTES), "r"(mbar)
            : "memory");
    }
    // all threads wait for the tile (parity 0)
    asm volatile(
        "{ .reg .pred P;\n"
        "W%=: mbarrier.try_wait.parity.acquire.cta.shared::cta.b64 P, [%0], 0;\n"
        "  @!P bra W%=;\n}"
        :: "r"(mbar) : "memory");

    // ---- Pass A: count-above + collect in-window (from SMEM, LDS.128) ----
    const float4* sr = (const float4*)s_row;
    {
        const unsigned curaddr = (unsigned)__cvta_generic_to_shared(&s_cur);
        const unsigned actbase = (unsigned)__cvta_generic_to_shared(s_act);
        int chi = 0;
#pragma unroll
        for (int i = 0; i < 4; ++i) {
            float4 v = sr[i * TPB + tid];
            passA_elem(v.x, chi, curaddr, actbase);
            passA_elem(v.y, chi, curaddr, actbase);
            passA_elem(v.z, chi, curaddr, actbase);
            passA_elem(v.w, chi, curaddr, actbase);
        }
        chi = __reduce_add_sync(0xFFFFFFFFu, chi);
        if (lane == 0) atomicAdd(&s_chi, chi);
    }
    __syncthreads();

    const int ncoll = s_cur;
    const int chi   = s_chi;
    const int nscan = (ncoll < MAXCOLL) ? ncoll : MAXCOLL;
    if (tid == 0 && ncoll > MAXCOLL) s_fb = 1;   // collect overflow -> fallback

    // ---- Pass B: histogram the collected (~371) into 186 key-domain bins ----
    for (int i = tid; i < nscan; i += TPB) {
        unsigned u = s_act[i];
        atomicAdd(&s_hist[(UB - 1u - u) >> BIN_SHIFT], 1);
    }
    __syncthreads();

    // ---- Pass C: warp-0 suffix scan; bucket j* with cum(j*)>=k>cum(j*+1) ----
    if (tid < 32) {
        int h[6];
        int lt = 0;
#pragma unroll
        for (int r = 0; r < 6; ++r) { h[r] = s_hist[lane * 6 + r]; lt += h[r]; }
        int x = lt;                                    // suffix sum over lanes
#pragma unroll
        for (int d = 1; d < 32; d <<= 1) {
            int y = __shfl_down_sync(0xFFFFFFFFu, x, d);
            if (lane + d < 32) x += y;
        }
        const int cumbase = chi + x;                   // count(bin >= 6*lane)
        int cand = -1, candcum = 0, candh = 0, pre = 0;
#pragma unroll
        for (int r = 0; r < 6; ++r) {
            int j   = lane * 6 + r;
            int cum = cumbase - pre;                   // count(bin >= j)
            if (cum >= kth) { cand = j; candcum = cum; candh = h[r]; }
            pre += h[r];
        }
        int jstar = __reduce_max_sync(0xFFFFFFFFu, cand);
        if (cand == jstar && jstar >= 0) {             // unique owner lane
            s_j = jstar;
            s_m = kth - (candcum - candh);
            s_nb = candh;
            if (candh > MAXB) s_fb = 1;
        }
        if (lane == 0 && (jstar < 0 || chi >= kth)) s_fb = 1;
    }
    __syncthreads();

    float ft;
    if (!s_fb) {
        // ---- Pass D: gather bucket members (<= 32) as keys ----
        const unsigned ubhi = UB - 1u - ((unsigned)s_j << BIN_SHIFT);
        for (int i = tid; i < nscan; i += TPB) {
            unsigned u = s_act[i];
            if ((ubhi - u) < (1u << BIN_SHIFT)) {
                int pos = atomicAdd(&s_cur2, 1);
                s_bucket[pos] = ~u;                    // key of negative float
            }
        }
        __syncthreads();

        // warp 0: m-th largest among <=32 keys (dup-safe)
        if (tid < 32) {
            const int nb = s_nb, m = s_m;
            unsigned kv = (lane < nb) ? s_bucket[lane] : 0u;
            for (int i = 1; i < m; ++i) {
                unsigned mx   = __reduce_max_sync(0xFFFFFFFFu, kv);
                unsigned ball = __ballot_sync(0xFFFFFFFFu, kv == mx);
                if (lane == (int)(__ffs(ball) - 1)) kv = 0u;
            }
            unsigned t = __reduce_max_sync(0xFFFFFFFFu, kv);
            if (lane == 0) s_ft = key2f(t);
        }
        __syncthreads();
        ft = s_ft;
    } else {
        // ---- exact fallback: 32-bit MSB-first descent over SMEM row ----
        unsigned result = 0u;
#pragma unroll 1
        for (int bit = 31; bit >= 0; --bit) {
            const unsigned t = result | (1u << bit);
            int c = 0;
#pragma unroll
            for (int i = 0; i < 4; ++i) {
                float4 v = sr[i * TPB + tid];
                c += (f2key(v.x) >= t) ? 1 : 0;
                c += (f2key(v.y) >= t) ? 1 : 0;
                c += (f2key(v.z) >= t) ? 1 : 0;
                c += (f2key(v.w) >= t) ? 1 : 0;
            }
            c = __reduce_add_sync(0xFFFFFFFFu, c);
            if (lane == 0) s_part[bit & 1][tid >> 5] = c;
            __syncthreads();
            int tot = 0;
#pragma unroll
            for (int w = 0; w < TPB / 32; ++w) tot += s_part[bit & 1][w];
            if (tot >= kth) { result = t; if (tot == kth) break; }   // uniform
        }
        ft = key2f(result);
    }

    // ---- output: threshold from smem in regs, STG.128 direct to GMEM ----
    {
        float4* q = out + (size_t)blockIdx.x * (N_COLS / 4) + tid;
#pragma unroll
        for (int i = 0; i < 4; ++i) {
            float4 v = sr[i * TPB + tid];
            v.x = (v.x >= ft) ? v.x : 0.0f;
            v.y = (v.y >= ft) ? v.y : 0.0f;
            v.z = (v.z >= ft) ? v.z : 0.0f;
            v.w = (v.w >= ft) ? v.w : 0.0f;
            q[i * TPB] = v;
        }
    }
}

extern "C" void kernel_launch(void* const* d_in, const int* in_sizes, int n_in,
                              void* d_out, int out_size)
{
    const float* in  = (const float*)d_in[0];
    float4*      out = (float4*)d_out;

    const int rows = in_sizes[0] / N_COLS;        // 8 * 4096 = 32768

    int k = (int)((double)N_COLS * (1.0 - 0.3));  // 2867, matches Python int()
    if (k < 1) k = 1;

    topk_sparsify_kernel<<<rows, TPB>>>(in, out, k);
}